// round 15
// baseline (speedup 1.0000x reference)
#include <cuda_runtime.h>
#include <cuda_fp16.h>
#include <math.h>
#include <stdint.h>

// ---------------- problem constants ----------------
#define HID 2048
#define NEXP 256
#define NGRP 8
#define TOPG 4
#define TOPK 8
#define RSCALE 2.5f
#define MT 128                 // tokens per CTA -> grid = 128 = ONE wave
#define KT 64                  // K per smem stage
#define NST (HID / KT)         // 32 stages

// ---------------- packed fp16 smem layout ----------------
// per row 32 pairs; words [2p]=hi f16x2, [2p+1]=lo f16x2; stride 72 words.
// rows 0..127 = A (tokens), rows 128..383 = B (experts).
#define RSPK 72
#define OFF_BIAS 0
#define OFF_PK 1024
#define PKSTAGE (384 * RSPK * 4)                 // 110592
#define SMEM_TOTAL (OFF_PK + 2 * PKSTAGE)        // 222208
#define SC_STRIDE 260

// W pre-split: [256 rows][1024 pairs] of uint2 {hi16x2, lo16x2} = 2 MB
__device__ uint2 g_wpk[NEXP * (HID / 2)];

#define MMA16(d, a, b) asm volatile( \
    "mma.sync.aligned.m16n8k16.row.col.f32.f16.f16.f32 " \
    "{%0,%1,%2,%3},{%4,%5,%6,%7},{%8,%9},{%0,%1,%2,%3};" \
    : "+f"((d)[0]), "+f"((d)[1]), "+f"((d)[2]), "+f"((d)[3]) \
    : "r"((a)[0]), "r"((a)[1]), "r"((a)[2]), "r"((a)[3]), \
      "r"((b)[0]), "r"((b)[1]))

#define CPA(dst, src) asm volatile( \
    "cp.async.cg.shared.global [%0], [%1], 16;" :: "r"(dst), "l"(src) : "memory")
#define CPA_COMMIT asm volatile("cp.async.commit_group;" ::: "memory")

static __device__ __forceinline__ uint32_t s2u(const void* p) {
    uint32_t r;
    asm("{ .reg .u64 t; cvta.to.shared.u64 t, %1; cvt.u32.u64 %0, t; }" : "=r"(r) : "l"(p));
    return r;
}
static __device__ __forceinline__ uint32_t h2u(__half2 h) {
    return *(uint32_t*)&h;
}

// split 2 floats -> {hi f16x2, lo f16x2}; lo UNSCALED (fp16 subnormals carry
// the tail for tiny residuals; error ~2^-25 absolute, negligible vs scores ~1)
static __device__ __forceinline__ uint2 packpair(float a, float b) {
    __half2 h = __floats2half2_rn(a, b);
    float2 f = __half22float2(h);
    __half2 l = __floats2half2_rn(a - f.x, b - f.y);
    uint2 r; r.x = h2u(h); r.y = h2u(l);
    return r;
}

// ---------------------------------------------------------------------------
// One-time W split: fp32 [256,2048] -> interleaved {hi,lo} fp16x2 pairs.
// ---------------------------------------------------------------------------
extern "C" __global__ void split_w_kernel(const float* __restrict__ w,
                                          uint2* __restrict__ wpk)
{
    int id = blockIdx.x * 512 + threadIdx.x;        // 131072 float4s
    float4 v = ((const float4*)w)[id];
    wpk[id * 2 + 0] = packpair(v.x, v.y);
    wpk[id * 2 + 1] = packpair(v.z, v.w);
}

// ---------------------------------------------------------------------------
// Fused: 3-term fp16 mma.sync GEMM (128 x 256 x 2048 per CTA), SINGLE fp32
// accumulator (hi*hi exact; unscaled cross terms), B pre-split (cp.async),
// A split in registers. 512 threads, 16 warps, 64x32 warp tiles, KT=64,
// grid=128 (one wave). + sigmoid + grouped top-k routing.
// ---------------------------------------------------------------------------
extern "C" __global__ void __launch_bounds__(512, 1)
gate_fused_kernel(const float* __restrict__ x,
                  const uint2* __restrict__ wpk,
                  const float* __restrict__ bias,
                  float* __restrict__ out, int N, int with_idx)
{
    extern __shared__ __align__(1024) char smem[];
    const uint32_t sb = s2u(smem);
    const int tid  = threadIdx.x;
    const int wid  = tid >> 5;
    const int lane = tid & 31;
    const int m0   = blockIdx.x * MT;
    const int wm   = wid & 1;      // 2 M-groups of 64 tokens
    const int wn   = wid >> 1;     // 8 N-groups of 32 experts

    float* bs = (float*)(smem + OFF_BIAS);
    if (tid < NEXP) bs[tid] = bias[tid];

    float acc[4][4][4];            // [mi: 4 x m16][ni: 4 x n8][4]
    #pragma unroll
    for (int i = 0; i < 4; i++)
        #pragma unroll
        for (int j = 0; j < 4; j++)
            #pragma unroll
            for (int c = 0; c < 4; c++) acc[i][j][c] = 0.0f;

    const int arow = tid >> 2;     // 0..127 (A row)
    const int achk = tid & 3;      // base float4 chunk; covers achk+4i, i<4

    // ---- A: LDG + register split + packed STS (4 float4 per thread) ----
    auto ldstA = [&](int s) {
        const float* p = x + (size_t)(m0 + arow) * HID + s * KT;
        uint32_t* pk = (uint32_t*)(smem + OFF_PK + (s & 1) * PKSTAGE);
        #pragma unroll
        for (int i = 0; i < 4; i++) {
            float4 v = *(const float4*)(p + (achk + 4 * i) * 4);
            uint2 p0 = packpair(v.x, v.y);
            uint2 p1 = packpair(v.z, v.w);
            uint4 o4; o4.x = p0.x; o4.y = p0.y; o4.z = p1.x; o4.w = p1.y;
            *(uint4*)(pk + arow * RSPK + (achk + 4 * i) * 4) = o4;
        }
    };
    // ---- B: cp.async packed tile (256 rows x 32 pairs = 64KB) ----
    auto cpaB = [&](int s) {
        const uint32_t bufa = sb + OFF_PK + (s & 1) * PKSTAGE;
        #pragma unroll
        for (int i = 0; i < 8; i++) {
            int id = tid + i * 512;            // 4096 16B-chunks
            int row = id >> 4, c = id & 15;
            uint32_t dst = bufa + (uint32_t)((MT + row) * RSPK + c * 4) * 4;
            CPA(dst, wpk + (size_t)row * (HID / 2) + s * 32 + 2 * c);
        }
        CPA_COMMIT;
    };

    auto compute = [&](int s) {
        const uint32_t* pk = (const uint32_t*)(smem + OFF_PK + (s & 1) * PKSTAGE);
        #pragma unroll
        for (int c = 0; c < 4; c++) {          // four k16 chunks per stage
            const int pbase = (c * 8 + (lane & 3)) * 2;
            uint32_t ah[4][4], al[4][4];
            #pragma unroll
            for (int mi = 0; mi < 4; mi++) {
                int r = wm * 64 + mi * 16 + (lane >> 2);
                int o = r * RSPK + pbase;
                uint2 w0 = *(const uint2*)(pk + o);
                uint2 w1 = *(const uint2*)(pk + o + 8 * RSPK);
                uint2 w2 = *(const uint2*)(pk + o + 8);
                uint2 w3 = *(const uint2*)(pk + o + 8 * RSPK + 8);
                ah[mi][0] = w0.x; al[mi][0] = w0.y;
                ah[mi][1] = w1.x; al[mi][1] = w1.y;
                ah[mi][2] = w2.x; al[mi][2] = w2.y;
                ah[mi][3] = w3.x; al[mi][3] = w3.y;
            }
            uint32_t bh[4][2], bl[4][2];
            #pragma unroll
            for (int ni = 0; ni < 4; ni++) {
                int e = wn * 32 + ni * 8 + (lane >> 2);
                int o = (MT + e) * RSPK + pbase;
                uint2 u0 = *(const uint2*)(pk + o);
                uint2 u1 = *(const uint2*)(pk + o + 8);
                bh[ni][0] = u0.x; bl[ni][0] = u0.y;
                bh[ni][1] = u1.x; bl[ni][1] = u1.y;
            }
            // term-major: same-accumulator reuse distance = 16 MMAs
            #pragma unroll
            for (int ni = 0; ni < 4; ni++)
                #pragma unroll
                for (int mi = 0; mi < 4; mi++)
                    MMA16(acc[mi][ni], ah[mi], bh[ni]);   // exact hi*hi
            #pragma unroll
            for (int ni = 0; ni < 4; ni++)
                #pragma unroll
                for (int mi = 0; mi < 4; mi++)
                    MMA16(acc[mi][ni], al[mi], bh[ni]);
            #pragma unroll
            for (int ni = 0; ni < 4; ni++)
                #pragma unroll
                for (int mi = 0; mi < 4; mi++)
                    MMA16(acc[mi][ni], ah[mi], bl[ni]);
        }
    };

    // ---- pipelined main loop: one barrier per 64-K stage ----
    cpaB(0);
    ldstA(0);
    for (int s = 0; s < NST; s++) {
        asm volatile("cp.async.wait_group 0;" ::: "memory");
        __syncthreads();     // B(s)+A(s) visible; compute(s-1) done
        if (s + 1 < NST) {
            cpaB(s + 1);     // other buffer; overlaps with compute(s)
            ldstA(s + 1);
        }
        compute(s);
    }
    __syncthreads();   // tiles dead; reuse smem for scores overlay

    // ---- epilogue: +bias, sigmoid, scores overlay ----
    float* sc = (float*)(smem + OFF_PK);
    #pragma unroll
    for (int mi = 0; mi < 4; mi++) {
        int tr = wm * 64 + mi * 16 + (lane >> 2);
        #pragma unroll
        for (int ni = 0; ni < 4; ni++) {
            int e = wn * 32 + ni * 8 + (lane & 3) * 2;
            float s0 = acc[mi][ni][0] + bs[e];
            float s1 = acc[mi][ni][1] + bs[e + 1];
            float s2 = acc[mi][ni][2] + bs[e];
            float s3 = acc[mi][ni][3] + bs[e + 1];
            float2 v0, v1;
            v0.x = 1.0f / (1.0f + expf(-s0));
            v0.y = 1.0f / (1.0f + expf(-s1));
            v1.x = 1.0f / (1.0f + expf(-s2));
            v1.y = 1.0f / (1.0f + expf(-s3));
            *(float2*)&sc[tr * SC_STRIDE + e]       = v0;
            *(float2*)&sc[(tr + 8) * SC_STRIDE + e] = v1;
        }
    }
    __syncthreads();

    // ---- routing: warp per token, 8 tokens per warp ----
    for (int it = 0; it < 8; it++) {
        const int t = wid * 8 + it;
        const float* row = sc + t * SC_STRIDE;

        float orig[NGRP], rsc[NGRP];
        #pragma unroll
        for (int s = 0; s < NGRP; s++) {
            float sg = row[s * 32 + lane];
            orig[s] = sg;
            rsc[s] = sg + bs[s * 32 + lane];
        }

        // group score = top-2 sum (ties -> lower expert index)
        float gs[NGRP];
        #pragma unroll
        for (int g = 0; g < NGRP; g++) {
            float m1 = rsc[g];
            int l1 = lane;
            #pragma unroll
            for (int off = 16; off >= 1; off >>= 1) {
                float ov = __shfl_xor_sync(0xffffffffu, m1, off);
                int ol = __shfl_xor_sync(0xffffffffu, l1, off);
                if (ov > m1 || (ov == m1 && ol < l1)) { m1 = ov; l1 = ol; }
            }
            float v2 = (lane == l1) ? -INFINITY : rsc[g];
            #pragma unroll
            for (int off = 16; off >= 1; off >>= 1)
                v2 = fmaxf(v2, __shfl_xor_sync(0xffffffffu, v2, off));
            gs[g] = m1 + v2;
        }

        // keep top-4 groups (ties -> lower group index)
        float mv[NGRP];
        #pragma unroll
        for (int g = 0; g < NGRP; g++) {
            int cnt = 0;
            #pragma unroll
            for (int h = 0; h < NGRP; h++)
                cnt += (gs[h] > gs[g]) || (gs[h] == gs[g] && h < g);
            mv[g] = (cnt < TOPG) ? rsc[g] : -INFINITY;
        }

        // iterative top-8 (ties -> lower expert index)
        float wsel[TOPK];
        int esel[TOPK];
        #pragma unroll
        for (int k = 0; k < TOPK; k++) {
            float bv2 = -INFINITY; int be = NEXP; float bo = 0.0f;
            #pragma unroll
            for (int s = 0; s < NGRP; s++)
                if (mv[s] > bv2) { bv2 = mv[s]; be = s * 32 + lane; bo = orig[s]; }
            #pragma unroll
            for (int off = 16; off >= 1; off >>= 1) {
                float ov = __shfl_xor_sync(0xffffffffu, bv2, off);
                int oe = __shfl_xor_sync(0xffffffffu, be, off);
                float oo = __shfl_xor_sync(0xffffffffu, bo, off);
                if (ov > bv2 || (ov == bv2 && oe < be)) { bv2 = ov; be = oe; bo = oo; }
            }
            wsel[k] = bo;
            esel[k] = be;
            if ((be & 31) == lane) {
                int bslot = be >> 5;
                #pragma unroll
                for (int s = 0; s < NGRP; s++)
                    if (s == bslot) mv[s] = -INFINITY;
            }
        }

        float tot = 0.0f;
        #pragma unroll
        for (int k = 0; k < TOPK; k++) tot += wsel[k];
        float inv = RSCALE / tot;

        const int gt = m0 + t;
        #pragma unroll
        for (int k = 0; k < TOPK; k++) {
            if (lane == k) {
                out[(size_t)gt * TOPK + k] = wsel[k] * inv;
                if (with_idx)
                    out[(size_t)N * TOPK + (size_t)gt * TOPK + k] = (float)esel[k];
            }
        }
    }
}

// ---------------------------------------------------------------------------
extern "C" void kernel_launch(void* const* d_in, const int* in_sizes, int n_in,
                              void* d_out, int out_size)
{
    const float* x    = (const float*)d_in[0];
    const float* w    = (const float*)d_in[1];
    const float* bias = (const float*)d_in[2];
    float* out = (float*)d_out;

    int N = in_sizes[0] / HID;
    int with_idx = (out_size >= 2 * N * TOPK) ? 1 : 0;

    uint2* wpk = nullptr;
    cudaGetSymbolAddress((void**)&wpk, g_wpk);

    split_w_kernel<<<NEXP * HID / 4 / 512, 512>>>(w, wpk);

    cudaFuncSetAttribute(gate_fused_kernel,
                         cudaFuncAttributeMaxDynamicSharedMemorySize, SMEM_TOTAL);
    gate_fused_kernel<<<N / MT, 512, SMEM_TOTAL>>>(x, wpk, bias, out, N, with_idx);
}

// round 16
// speedup vs baseline: 1.1023x; 1.1023x over previous
#include <cuda_runtime.h>
#include <cuda_fp16.h>
#include <math.h>
#include <stdint.h>

// ---------------- problem constants ----------------
#define HID 2048
#define NEXP 256
#define NGRP 8
#define TOPG 4
#define TOPK 8
#define RSCALE 2.5f
#define MT 64                  // tokens per CTA
#define KT 64                  // K per smem stage
#define NST (HID / KT)         // 32 stages

// ---------------- quad-packed fp16 smem layout ----------------
// Quad (16B) = [hi(p), lo(p), hi(p+4), lo(p+4)] : exactly the (k, k+8) halves
// one m16n8k16 fragment element needs -> every frag load is ONE LDS.128.
// Per row: 16 quads per stage (64 words), stride 80 words (conflict-free).
// rows 0..63 = A (tokens), rows 64..319 = B (experts).
#define RSW 80
#define OFF_BIAS 0
#define OFF_PK 1024
#define PKSTAGE (320 * RSW * 4)                  // 102400
#define SMEM_TOTAL (OFF_PK + 2 * PKSTAGE)        // 205824
#define SC_STRIDE 260

// W pre-split, quad layout: [256 rows][2048 words] = 2 MB
__device__ uint32_t g_wq[NEXP * 2048];

#define MMA16(d, a, b) asm volatile( \
    "mma.sync.aligned.m16n8k16.row.col.f32.f16.f16.f32 " \
    "{%0,%1,%2,%3},{%4,%5,%6,%7},{%8,%9},{%0,%1,%2,%3};" \
    : "+f"((d)[0]), "+f"((d)[1]), "+f"((d)[2]), "+f"((d)[3]) \
    : "r"((a)[0]), "r"((a)[1]), "r"((a)[2]), "r"((a)[3]), \
      "r"((b)[0]), "r"((b)[1]))

#define CPA(dst, src) asm volatile( \
    "cp.async.cg.shared.global [%0], [%1], 16;" :: "r"(dst), "l"(src) : "memory")
#define CPA_COMMIT asm volatile("cp.async.commit_group;" ::: "memory")

static __device__ __forceinline__ uint32_t s2u(const void* p) {
    uint32_t r;
    asm("{ .reg .u64 t; cvta.to.shared.u64 t, %1; cvt.u32.u64 %0, t; }" : "=r"(r) : "l"(p));
    return r;
}
static __device__ __forceinline__ uint32_t h2u(__half2 h) {
    return *(uint32_t*)&h;
}

// split 2 floats (one k-pair) -> {hi f16x2, lo f16x2}; lo unscaled
static __device__ __forceinline__ uint2 packpair(float a, float b) {
    __half2 h = __floats2half2_rn(a, b);
    float2 f = __half22float2(h);
    __half2 l = __floats2half2_rn(a - f.x, b - f.y);
    uint2 r; r.x = h2u(h); r.y = h2u(l);
    return r;
}

// quad word offset of k-pair p within a row: c=p>>3, t=p&3, h=(p>>2)&1
static __device__ __forceinline__ int wq_off(int p) {
    return 16 * (p >> 3) + 4 * (p & 3) + 2 * ((p >> 2) & 1);
}

// ---------------------------------------------------------------------------
// One-time W split into quad layout.
// ---------------------------------------------------------------------------
extern "C" __global__ void split_w_kernel(const float* __restrict__ w,
                                          uint32_t* __restrict__ wq)
{
    int id = blockIdx.x * 512 + threadIdx.x;        // 131072 float4s
    int row = id >> 9, j = id & 511;                // pairs 2j, 2j+1
    float4 v = ((const float4*)w)[id];
    uint2 p0 = packpair(v.x, v.y);
    uint2 p1 = packpair(v.z, v.w);
    *(uint2*)(wq + (size_t)row * 2048 + wq_off(2 * j))     = p0;
    *(uint2*)(wq + (size_t)row * 2048 + wq_off(2 * j + 1)) = p1;
}

// ---------------------------------------------------------------------------
// Fused 3-term fp16 mma.sync GEMM (64 x 256 x 2048 per CTA), single fp32
// accumulator, quad-packed tiles (all frag loads LDS.128), B pre-split
// (cp.async), A split in registers. 512 threads, 16 warps, 32x32 warp tiles,
// KT=64, one barrier per stage. + sigmoid + grouped top-k routing.
// ---------------------------------------------------------------------------
extern "C" __global__ void __launch_bounds__(512, 1)
gate_fused_kernel(const float* __restrict__ x,
                  const uint32_t* __restrict__ wq,
                  const float* __restrict__ bias,
                  float* __restrict__ out, int N, int with_idx)
{
    extern __shared__ __align__(1024) char smem[];
    const uint32_t sb = s2u(smem);
    const int tid  = threadIdx.x;
    const int wid  = tid >> 5;
    const int lane = tid & 31;
    const int m0   = blockIdx.x * MT;
    const int wm   = wid & 1;      // 2 M-groups of 32 tokens
    const int wn   = wid >> 1;     // 8 N-groups of 32 experts

    float* bs = (float*)(smem + OFF_BIAS);
    if (tid < NEXP) bs[tid] = bias[tid];

    float acc[2][4][4];
    #pragma unroll
    for (int i = 0; i < 2; i++)
        #pragma unroll
        for (int j = 0; j < 4; j++)
            #pragma unroll
            for (int c = 0; c < 4; c++) acc[i][j][c] = 0.0f;

    // ---- A producer: 1024 quads/stage, 2 per thread (rows tid>>4, +32) ----
    const int prow = tid >> 4;     // 0..31
    const int pqi  = tid & 15;     // quad index within stage
    const int pk0  = (pqi >> 2) * 16 + (pqi & 3) * 2;   // k offset of pair

    struct APre { float2 a0, b0, a1, b1; };
    auto ldgA = [&](int s, APre& v) {
        const float* p1 = x + (size_t)(m0 + prow) * HID + s * KT + pk0;
        v.a0 = *(const float2*)p1;
        v.b0 = *(const float2*)(p1 + 8);
        const float* p2 = p1 + (size_t)32 * HID;
        v.a1 = *(const float2*)p2;
        v.b1 = *(const float2*)(p2 + 8);
    };
    auto stsA = [&](int s, const APre& v) {
        uint32_t* pk = (uint32_t*)(smem + OFF_PK + (s & 1) * PKSTAGE);
        uint2 q0 = packpair(v.a0.x, v.a0.y);
        uint2 q1 = packpair(v.b0.x, v.b0.y);
        uint4 o; o.x = q0.x; o.y = q0.y; o.z = q1.x; o.w = q1.y;
        *(uint4*)(pk + prow * RSW + pqi * 4) = o;
        uint2 q2 = packpair(v.a1.x, v.a1.y);
        uint2 q3 = packpair(v.b1.x, v.b1.y);
        uint4 o2; o2.x = q2.x; o2.y = q2.y; o2.z = q3.x; o2.w = q3.y;
        *(uint4*)(pk + (prow + 32) * RSW + pqi * 4) = o2;
    };
    // ---- B: cp.async quad tile (256 rows x 16 quads = 64KB) ----
    auto cpaB = [&](int s) {
        const uint32_t bufa = sb + OFF_PK + (s & 1) * PKSTAGE;
        #pragma unroll
        for (int i = 0; i < 8; i++) {
            int id = tid + i * 512;            // 4096 quads
            int row = id >> 4, qi = id & 15;
            uint32_t dst = bufa + (uint32_t)((64 + row) * RSW + qi * 4) * 4;
            CPA(dst, wq + (size_t)row * 2048 + s * 64 + qi * 4);
        }
        CPA_COMMIT;
    };

    auto compute = [&](int s) {
        const uint32_t* pk = (const uint32_t*)(smem + OFF_PK + (s & 1) * PKSTAGE);
        const int t = lane & 3, g = lane >> 2;
        #pragma unroll
        for (int c = 0; c < 4; c++) {          // four k16 chunks per stage
            const int co = c * 16 + t * 4;
            uint32_t ah[2][4], al[2][4];
            #pragma unroll
            for (int mi = 0; mi < 2; mi++) {
                int r = wm * 32 + mi * 16 + g;
                uint4 u0 = *(const uint4*)(pk + r * RSW + co);
                uint4 u1 = *(const uint4*)(pk + (r + 8) * RSW + co);
                ah[mi][0] = u0.x; al[mi][0] = u0.y;
                ah[mi][2] = u0.z; al[mi][2] = u0.w;
                ah[mi][1] = u1.x; al[mi][1] = u1.y;
                ah[mi][3] = u1.z; al[mi][3] = u1.w;
            }
            uint32_t bh[4][2], bl[4][2];
            #pragma unroll
            for (int ni = 0; ni < 4; ni++) {
                int e = 64 + wn * 32 + ni * 8 + g;
                uint4 u = *(const uint4*)(pk + e * RSW + co);
                bh[ni][0] = u.x; bl[ni][0] = u.y;
                bh[ni][1] = u.z; bl[ni][1] = u.w;
            }
            // term-major, single accumulator (reuse distance 8 MMAs)
            #pragma unroll
            for (int ni = 0; ni < 4; ni++)
                #pragma unroll
                for (int mi = 0; mi < 2; mi++)
                    MMA16(acc[mi][ni], ah[mi], bh[ni]);   // exact hi*hi
            #pragma unroll
            for (int ni = 0; ni < 4; ni++)
                #pragma unroll
                for (int mi = 0; mi < 2; mi++)
                    MMA16(acc[mi][ni], al[mi], bh[ni]);
            #pragma unroll
            for (int ni = 0; ni < 4; ni++)
                #pragma unroll
                for (int mi = 0; mi < 2; mi++)
                    MMA16(acc[mi][ni], ah[mi], bl[ni]);
        }
    };

    // ---- pipelined main loop: one barrier per 64-K stage ----
    APre avA, avB;
    cpaB(0);
    ldgA(0, avA);
    stsA(0, avA);
    ldgA(1, avB);
    for (int s = 0; s < NST; s++) {
        asm volatile("cp.async.wait_group 0;" ::: "memory");
        __syncthreads();     // B(s)+A(s) visible; compute(s-1) done
        if (s + 1 < NST) {
            cpaB(s + 1);                          // other buffer
            stsA(s + 1, (s & 1) ? avA : avB);
            if (s + 2 < NST) {
                if (s & 1) ldgA(s + 2, avB);
                else       ldgA(s + 2, avA);
            }
        }
        compute(s);
    }
    __syncthreads();   // tiles dead; reuse smem for scores overlay

    // ---- epilogue: +bias, sigmoid, scores overlay ----
    float* sc = (float*)(smem + OFF_PK);
    #pragma unroll
    for (int mi = 0; mi < 2; mi++) {
        int tr = wm * 32 + mi * 16 + (lane >> 2);
        #pragma unroll
        for (int ni = 0; ni < 4; ni++) {
            int e = wn * 32 + ni * 8 + (lane & 3) * 2;
            float s0 = acc[mi][ni][0] + bs[e];
            float s1 = acc[mi][ni][1] + bs[e + 1];
            float s2 = acc[mi][ni][2] + bs[e];
            float s3 = acc[mi][ni][3] + bs[e + 1];
            float2 v0, v1;
            v0.x = 1.0f / (1.0f + expf(-s0));
            v0.y = 1.0f / (1.0f + expf(-s1));
            v1.x = 1.0f / (1.0f + expf(-s2));
            v1.y = 1.0f / (1.0f + expf(-s3));
            *(float2*)&sc[tr * SC_STRIDE + e]       = v0;
            *(float2*)&sc[(tr + 8) * SC_STRIDE + e] = v1;
        }
    }
    __syncthreads();

    // ---- routing: warp per token, 4 tokens per warp ----
    for (int it = 0; it < 4; it++) {
        const int t = wid * 4 + it;
        const float* row = sc + t * SC_STRIDE;

        float orig[NGRP], rsc[NGRP];
        #pragma unroll
        for (int s = 0; s < NGRP; s++) {
            float sg = row[s * 32 + lane];
            orig[s] = sg;
            rsc[s] = sg + bs[s * 32 + lane];
        }

        // group score = top-2 sum (ties -> lower expert index)
        float gs[NGRP];
        #pragma unroll
        for (int g = 0; g < NGRP; g++) {
            float m1 = rsc[g];
            int l1 = lane;
            #pragma unroll
            for (int off = 16; off >= 1; off >>= 1) {
                float ov = __shfl_xor_sync(0xffffffffu, m1, off);
                int ol = __shfl_xor_sync(0xffffffffu, l1, off);
                if (ov > m1 || (ov == m1 && ol < l1)) { m1 = ov; l1 = ol; }
            }
            float v2 = (lane == l1) ? -INFINITY : rsc[g];
            #pragma unroll
            for (int off = 16; off >= 1; off >>= 1)
                v2 = fmaxf(v2, __shfl_xor_sync(0xffffffffu, v2, off));
            gs[g] = m1 + v2;
        }

        // keep top-4 groups (ties -> lower group index)
        float mv[NGRP];
        #pragma unroll
        for (int g = 0; g < NGRP; g++) {
            int cnt = 0;
            #pragma unroll
            for (int h = 0; h < NGRP; h++)
                cnt += (gs[h] > gs[g]) || (gs[h] == gs[g] && h < g);
            mv[g] = (cnt < TOPG) ? rsc[g] : -INFINITY;
        }

        // iterative top-8 (ties -> lower expert index)
        float wsel[TOPK];
        int esel[TOPK];
        #pragma unroll
        for (int k = 0; k < TOPK; k++) {
            float bv2 = -INFINITY; int be = NEXP; float bo = 0.0f;
            #pragma unroll
            for (int s = 0; s < NGRP; s++)
                if (mv[s] > bv2) { bv2 = mv[s]; be = s * 32 + lane; bo = orig[s]; }
            #pragma unroll
            for (int off = 16; off >= 1; off >>= 1) {
                float ov = __shfl_xor_sync(0xffffffffu, bv2, off);
                int oe = __shfl_xor_sync(0xffffffffu, be, off);
                float oo = __shfl_xor_sync(0xffffffffu, bo, off);
                if (ov > bv2 || (ov == bv2 && oe < be)) { bv2 = ov; be = oe; bo = oo; }
            }
            wsel[k] = bo;
            esel[k] = be;
            if ((be & 31) == lane) {
                int bslot = be >> 5;
                #pragma unroll
                for (int s = 0; s < NGRP; s++)
                    if (s == bslot) mv[s] = -INFINITY;
            }
        }

        float tot = 0.0f;
        #pragma unroll
        for (int k = 0; k < TOPK; k++) tot += wsel[k];
        float inv = RSCALE / tot;

        const int gt = m0 + t;
        #pragma unroll
        for (int k = 0; k < TOPK; k++) {
            if (lane == k) {
                out[(size_t)gt * TOPK + k] = wsel[k] * inv;
                if (with_idx)
                    out[(size_t)N * TOPK + (size_t)gt * TOPK + k] = (float)esel[k];
            }
        }
    }
}

// ---------------------------------------------------------------------------
extern "C" void kernel_launch(void* const* d_in, const int* in_sizes, int n_in,
                              void* d_out, int out_size)
{
    const float* x    = (const float*)d_in[0];
    const float* w    = (const float*)d_in[1];
    const float* bias = (const float*)d_in[2];
    float* out = (float*)d_out;

    int N = in_sizes[0] / HID;
    int with_idx = (out_size >= 2 * N * TOPK) ? 1 : 0;

    uint32_t* wq = nullptr;
    cudaGetSymbolAddress((void**)&wq, g_wq);

    split_w_kernel<<<NEXP * HID / 4 / 512, 512>>>(w, wq);

    cudaFuncSetAttribute(gate_fused_kernel,
                         cudaFuncAttributeMaxDynamicSharedMemorySize, SMEM_TOTAL);
    gate_fused_kernel<<<N / MT, 512, SMEM_TOTAL>>>(x, wq, bias, out, N, with_idx);
}